// round 5
// baseline (speedup 1.0000x reference)
#include <cuda_runtime.h>

#define KCODES 256
#define DIM 32
#define TPB 128
#define NBLOCKS 608      // 4 CTAs/SM on 152 SMs -> single wave

// Codebook dims 16..31 served from the constant port (uniform index),
// keeping them off the L1/shared data path.
__constant__ float cb_c[KCODES * DIM];

__global__ void vq_zero_counts(float* counts) {
    counts[threadIdx.x] = 0.0f;
}

__global__ __launch_bounds__(TPB, 4) void vq_main(
    const float* __restrict__ x,
    const float* __restrict__ cb,
    float* __restrict__ out_rot,
    float* __restrict__ out_idx,
    float* __restrict__ out_counts,
    int nPairs)
{
    __shared__ __align__(16) float cb_lo[KCODES * 16];   // dims 0..15, 16 KB
    __shared__ float c2_s[KCODES];
    __shared__ float hist[KCODES];

    const int tid = threadIdx.x;

    // --- Stage dims 0..15 into shared; c2 exact (rounded squares, sequential sum) ---
    for (int k = tid; k < KCODES; k += TPB) {
        const float4* src = reinterpret_cast<const float4*>(cb + k * DIM);
        float4* dst = reinterpret_cast<float4*>(cb_lo + k * 16);
        float row[DIM];
        #pragma unroll
        for (int j = 0; j < 8; j++) {
            float4 v = src[j];
            row[4*j+0] = v.x; row[4*j+1] = v.y; row[4*j+2] = v.z; row[4*j+3] = v.w;
            if (j < 4) dst[j] = v;
        }
        float s = 0.0f;
        #pragma unroll
        for (int d = 0; d < DIM; d++)
            s = __fadd_rn(s, __fmul_rn(row[d], row[d]));
        c2_s[k] = s;
        hist[k] = 0.0f;
    }
    __syncthreads();

    // Balanced contiguous pair ranges per block (single wave).
    const int ps = (int)(((long long)blockIdx.x * nPairs) / NBLOCKS);
    const int pe = (int)(((long long)(blockIdx.x + 1) * nPairs) / NBLOCKS);

    for (int p = ps + tid; p < pe; p += TPB) {
        const float* xb = x + (long long)p * (2 * DIM);

        // Two tokens into registers; x2 sequential ascending d (reference order).
        float xr[2][DIM];
        float x2v[2];
        #pragma unroll
        for (int t = 0; t < 2; t++) {
            #pragma unroll
            for (int j = 0; j < 8; j++) {
                float4 v = reinterpret_cast<const float4*>(xb + t * DIM)[j];
                xr[t][4*j+0] = v.x; xr[t][4*j+1] = v.y;
                xr[t][4*j+2] = v.z; xr[t][4*j+3] = v.w;
            }
            float s = 0.0f;
            #pragma unroll
            for (int d = 0; d < DIM; d++)
                s = __fadd_rn(s, __fmul_rn(xr[t][d], xr[t][d]));
            x2v[t] = s;
        }

        float best[2] = {3.4e38f, 3.4e38f};
        int   bi[2]   = {0, 0};

        // --- Argmin scan: 2 codes/iter × 2 tokens, scalar FFMA + SEL updates ---
        #pragma unroll 1
        for (int k = 0; k < KCODES; k += 2) {
            float da[2] = {0.f, 0.f};
            float db[2] = {0.f, 0.f};

            // dims 0..15 from shared (broadcast LDS.128)
            #pragma unroll
            for (int jj = 0; jj < 4; jj++) {
                float4 ca = reinterpret_cast<const float4*>(cb_lo +  k      * 16)[jj];
                float4 cc = reinterpret_cast<const float4*>(cb_lo + (k + 1) * 16)[jj];
                const int d = 4 * jj;
                #pragma unroll
                for (int t = 0; t < 2; t++) {
                    da[t] = __fmaf_rn(xr[t][d+0], ca.x, da[t]);
                    da[t] = __fmaf_rn(xr[t][d+1], ca.y, da[t]);
                    da[t] = __fmaf_rn(xr[t][d+2], ca.z, da[t]);
                    da[t] = __fmaf_rn(xr[t][d+3], ca.w, da[t]);
                    db[t] = __fmaf_rn(xr[t][d+0], cc.x, db[t]);
                    db[t] = __fmaf_rn(xr[t][d+1], cc.y, db[t]);
                    db[t] = __fmaf_rn(xr[t][d+2], cc.z, db[t]);
                    db[t] = __fmaf_rn(xr[t][d+3], cc.w, db[t]);
                }
            }
            // dims 16..31 from constant port
            #pragma unroll
            for (int jj = 0; jj < 4; jj++) {
                float4 ca = reinterpret_cast<const float4*>(cb_c +  k      * DIM + 16)[jj];
                float4 cc = reinterpret_cast<const float4*>(cb_c + (k + 1) * DIM + 16)[jj];
                const int d = 16 + 4 * jj;
                #pragma unroll
                for (int t = 0; t < 2; t++) {
                    da[t] = __fmaf_rn(xr[t][d+0], ca.x, da[t]);
                    da[t] = __fmaf_rn(xr[t][d+1], ca.y, da[t]);
                    da[t] = __fmaf_rn(xr[t][d+2], ca.z, da[t]);
                    da[t] = __fmaf_rn(xr[t][d+3], ca.w, da[t]);
                    db[t] = __fmaf_rn(xr[t][d+0], cc.x, db[t]);
                    db[t] = __fmaf_rn(xr[t][d+1], cc.y, db[t]);
                    db[t] = __fmaf_rn(xr[t][d+2], cc.z, db[t]);
                    db[t] = __fmaf_rn(xr[t][d+3], cc.w, db[t]);
                }
            }

            // d2 = fl(fl(x2 - 2*dot) + c2); strict <, ascending k = first-index ties.
            // Ternary form -> FSETP + SEL (pred-as-data, lat 4), no guarded branches.
            const float c2a = c2_s[k], c2b = c2_s[k + 1];
            #pragma unroll
            for (int t = 0; t < 2; t++) {
                float v1 = __fadd_rn(__fadd_rn(x2v[t], __fmul_rn(-2.0f, da[t])), c2a);
                bool  u1 = v1 < best[t];
                best[t] = u1 ? v1 : best[t];
                bi[t]   = u1 ? k  : bi[t];
                float v2 = __fadd_rn(__fadd_rn(x2v[t], __fmul_rn(-2.0f, db[t])), c2b);
                bool  u2 = v2 < best[t];
                best[t] = u2 ? v2    : best[t];
                bi[t]   = u2 ? k + 1 : bi[t];
            }
        }

        // --- Per-token epilogue: histogram + rotation-trick output ---
        #pragma unroll
        for (int t = 0; t < 2; t++) {
            const int code = bi[t];
            atomicAdd(&hist[code], 1.0f);

            float qv[DIM];
            const float4* qrow = reinterpret_cast<const float4*>(cb + code * DIM);
            #pragma unroll
            for (int j = 0; j < 8; j++) {
                float4 v = __ldg(qrow + j);
                qv[4*j+0] = v.x; qv[4*j+1] = v.y; qv[4*j+2] = v.z; qv[4*j+3] = v.w;
            }

            float q2 = 0.f, dotq = 0.f;
            #pragma unroll
            for (int d = 0; d < DIM; d++) {
                q2   = __fmaf_rn(qv[d], qv[d], q2);
                dotq = __fmaf_rn(xr[t][d], qv[d], dotq);
            }
            const float eps = 1e-6f;
            const float x2t = x2v[t];
            float inx = 1.0f / fmaxf(sqrtf(x2t), eps);
            float inq = 1.0f / fmaxf(sqrtf(q2),  eps);
            float u2  = x2t * inx * inx;
            float qh2 = q2  * inq * inq;
            float uq  = dotq * inx * inq;
            float w2  = u2 + qh2 + 2.0f * uq;
            float iw  = 1.0f / fmaxf(sqrtf(w2), eps);
            float ew_un = x2t * inx + dotq * inq;
            float ew  = ew_un * iw;
            float eu  = x2t * inx;
            float a   = -2.0f * ew * iw;
            float s1  = 1.0f + a * inx;
            float s2  = (a + 2.0f * eu) * inq;

            float4* rp = reinterpret_cast<float4*>(out_rot + ((long long)p * 2 + t) * DIM);
            #pragma unroll
            for (int j = 0; j < 8; j++) {
                float4 v;
                v.x = xr[t][4*j+0] * s1 + qv[4*j+0] * s2;
                v.y = xr[t][4*j+1] * s1 + qv[4*j+1] * s2;
                v.z = xr[t][4*j+2] * s1 + qv[4*j+2] * s2;
                v.w = xr[t][4*j+3] * s1 + qv[4*j+3] * s2;
                rp[j] = v;
            }
            out_idx[(long long)p * 2 + t] = (float)code;
        }
    }

    // --- Flush block-local histogram ---
    __syncthreads();
    for (int k = tid; k < KCODES; k += TPB)
        atomicAdd(&out_counts[k], hist[k]);
}

extern "C" void kernel_launch(void* const* d_in, const int* in_sizes, int n_in,
                              void* d_out, int out_size) {
    const float* x  = (const float*)d_in[0];
    const float* cb = (const float*)d_in[1];
    float* out = (float*)d_out;

    const int N = in_sizes[0] / DIM;            // 524288
    const int nPairs = N / 2;                   // 262144
    float* rot    = out;
    float* idx    = out + (size_t)N * DIM;
    float* counts = idx + N;

    cudaMemcpyToSymbolAsync(cb_c, cb, KCODES * DIM * sizeof(float), 0,
                            cudaMemcpyDeviceToDevice, 0);
    vq_zero_counts<<<1, KCODES>>>(counts);
    vq_main<<<NBLOCKS, TPB>>>(x, cb, rot, idx, counts, nPairs);
}

// round 6
// speedup vs baseline: 1.2264x; 1.2264x over previous
#include <cuda_runtime.h>

#define KCODES 256
#define DIM 32
#define TPB 128
#define NBLOCKS 456      // 3 CTAs/SM on 152 SMs -> single wave

// Codebook dims 16..31 served from the constant port (uniform index),
// keeping them off the L1/shared data path.
__constant__ float cb_c[KCODES * DIM];

__global__ void vq_zero_counts(float* counts) {
    counts[threadIdx.x] = 0.0f;
}

// 8-way chain-interleaved FMA block: for one scalar code value pair (a from
// code k, b from code k+1) at dimension d, update all 8 accumulators before
// the next dimension is touched (>= 8 instr between same-chain uses).
#define FMA8(d, aval, bval)                                   \
    da0 = __fmaf_rn(xr0[d], (aval), da0);                     \
    da1 = __fmaf_rn(xr1[d], (aval), da1);                     \
    da2 = __fmaf_rn(xr2[d], (aval), da2);                     \
    da3 = __fmaf_rn(xr3[d], (aval), da3);                     \
    db0 = __fmaf_rn(xr0[d], (bval), db0);                     \
    db1 = __fmaf_rn(xr1[d], (bval), db1);                     \
    db2 = __fmaf_rn(xr2[d], (bval), db2);                     \
    db3 = __fmaf_rn(xr3[d], (bval), db3);

__global__ __launch_bounds__(TPB, 3) void vq_main(
    const float* __restrict__ x,
    const float* __restrict__ cb,
    float* __restrict__ out_rot,
    float* __restrict__ out_idx,
    float* __restrict__ out_counts,
    int nQuads)
{
    __shared__ __align__(16) float cb_lo[KCODES * 16];   // dims 0..15, 16 KB
    __shared__ float c2_s[KCODES];
    __shared__ float hist[KCODES];

    const int tid = threadIdx.x;

    // --- Stage dims 0..15 into shared; c2 exact (rounded squares, sequential sum) ---
    for (int k = tid; k < KCODES; k += TPB) {
        const float4* src = reinterpret_cast<const float4*>(cb + k * DIM);
        float4* dst = reinterpret_cast<float4*>(cb_lo + k * 16);
        float row[DIM];
        #pragma unroll
        for (int j = 0; j < 8; j++) {
            float4 v = src[j];
            row[4*j+0] = v.x; row[4*j+1] = v.y; row[4*j+2] = v.z; row[4*j+3] = v.w;
            if (j < 4) dst[j] = v;
        }
        float s = 0.0f;
        #pragma unroll
        for (int d = 0; d < DIM; d++)
            s = __fadd_rn(s, __fmul_rn(row[d], row[d]));
        c2_s[k] = s;
        hist[k] = 0.0f;
    }
    __syncthreads();

    const int qs = (int)(((long long)blockIdx.x * nQuads) / NBLOCKS);
    const int qe = (int)(((long long)(blockIdx.x + 1) * nQuads) / NBLOCKS);

    for (int q = qs + tid; q < qe; q += TPB) {
        const float* xb = x + (long long)q * (4 * DIM);

        // Four tokens in registers; x2 sequential ascending d (reference order).
        float xr0[DIM], xr1[DIM], xr2[DIM], xr3[DIM];
        float x2v[4];
        {
            #pragma unroll
            for (int j = 0; j < 8; j++) {
                float4 v0 = reinterpret_cast<const float4*>(xb        )[j];
                float4 v1 = reinterpret_cast<const float4*>(xb +   DIM)[j];
                float4 v2 = reinterpret_cast<const float4*>(xb + 2*DIM)[j];
                float4 v3 = reinterpret_cast<const float4*>(xb + 3*DIM)[j];
                xr0[4*j+0]=v0.x; xr0[4*j+1]=v0.y; xr0[4*j+2]=v0.z; xr0[4*j+3]=v0.w;
                xr1[4*j+0]=v1.x; xr1[4*j+1]=v1.y; xr1[4*j+2]=v1.z; xr1[4*j+3]=v1.w;
                xr2[4*j+0]=v2.x; xr2[4*j+1]=v2.y; xr2[4*j+2]=v2.z; xr2[4*j+3]=v2.w;
                xr3[4*j+0]=v3.x; xr3[4*j+1]=v3.y; xr3[4*j+2]=v3.z; xr3[4*j+3]=v3.w;
            }
            float s0=0.f, s1=0.f, s2=0.f, s3=0.f;
            #pragma unroll
            for (int d = 0; d < DIM; d++) {
                s0 = __fadd_rn(s0, __fmul_rn(xr0[d], xr0[d]));
                s1 = __fadd_rn(s1, __fmul_rn(xr1[d], xr1[d]));
                s2 = __fadd_rn(s2, __fmul_rn(xr2[d], xr2[d]));
                s3 = __fadd_rn(s3, __fmul_rn(xr3[d], xr3[d]));
            }
            x2v[0]=s0; x2v[1]=s1; x2v[2]=s2; x2v[3]=s3;
        }

        float best[4] = {3.4e38f, 3.4e38f, 3.4e38f, 3.4e38f};
        int   bi[4]   = {0, 0, 0, 0};

        // --- Argmin scan: 2 codes/iter × 4 tokens, chain-interleaved FFMA ---
        #pragma unroll 1
        for (int k = 0; k < KCODES; k += 2) {
            float da0=0.f, da1=0.f, da2=0.f, da3=0.f;
            float db0=0.f, db1=0.f, db2=0.f, db3=0.f;

            // dims 0..15 from shared (broadcast LDS.128)
            #pragma unroll
            for (int jj = 0; jj < 4; jj++) {
                float4 ca = reinterpret_cast<const float4*>(cb_lo +  k      * 16)[jj];
                float4 cc = reinterpret_cast<const float4*>(cb_lo + (k + 1) * 16)[jj];
                const int d = 4 * jj;
                FMA8(d + 0, ca.x, cc.x)
                FMA8(d + 1, ca.y, cc.y)
                FMA8(d + 2, ca.z, cc.z)
                FMA8(d + 3, ca.w, cc.w)
            }
            // dims 16..31 from constant port
            #pragma unroll
            for (int jj = 0; jj < 4; jj++) {
                float4 ca = reinterpret_cast<const float4*>(cb_c +  k      * DIM + 16)[jj];
                float4 cc = reinterpret_cast<const float4*>(cb_c + (k + 1) * DIM + 16)[jj];
                const int d = 16 + 4 * jj;
                FMA8(d + 0, ca.x, cc.x)
                FMA8(d + 1, ca.y, cc.y)
                FMA8(d + 2, ca.z, cc.z)
                FMA8(d + 3, ca.w, cc.w)
            }

            // d2 = fl(fl(x2 - 2*dot) + c2); strict <, ascending k = first-index ties
            const float c2a = c2_s[k], c2b = c2_s[k + 1];
            float va0 = __fadd_rn(__fadd_rn(x2v[0], __fmul_rn(-2.0f, da0)), c2a);
            float va1 = __fadd_rn(__fadd_rn(x2v[1], __fmul_rn(-2.0f, da1)), c2a);
            float va2 = __fadd_rn(__fadd_rn(x2v[2], __fmul_rn(-2.0f, da2)), c2a);
            float va3 = __fadd_rn(__fadd_rn(x2v[3], __fmul_rn(-2.0f, da3)), c2a);
            float vb0 = __fadd_rn(__fadd_rn(x2v[0], __fmul_rn(-2.0f, db0)), c2b);
            float vb1 = __fadd_rn(__fadd_rn(x2v[1], __fmul_rn(-2.0f, db1)), c2b);
            float vb2 = __fadd_rn(__fadd_rn(x2v[2], __fmul_rn(-2.0f, db2)), c2b);
            float vb3 = __fadd_rn(__fadd_rn(x2v[3], __fmul_rn(-2.0f, db3)), c2b);
            bool u;
            u = va0 < best[0]; best[0] = u ? va0 : best[0]; bi[0] = u ? k : bi[0];
            u = va1 < best[1]; best[1] = u ? va1 : best[1]; bi[1] = u ? k : bi[1];
            u = va2 < best[2]; best[2] = u ? va2 : best[2]; bi[2] = u ? k : bi[2];
            u = va3 < best[3]; best[3] = u ? va3 : best[3]; bi[3] = u ? k : bi[3];
            u = vb0 < best[0]; best[0] = u ? vb0 : best[0]; bi[0] = u ? k+1 : bi[0];
            u = vb1 < best[1]; best[1] = u ? vb1 : best[1]; bi[1] = u ? k+1 : bi[1];
            u = vb2 < best[2]; best[2] = u ? vb2 : best[2]; bi[2] = u ? k+1 : bi[2];
            u = vb3 < best[3]; best[3] = u ? vb3 : best[3]; bi[3] = u ? k+1 : bi[3];
        }

        // --- Per-token epilogue: histogram + rotation-trick output ---
        #pragma unroll
        for (int t = 0; t < 4; t++) {
            const float* xrt = (t == 0) ? xr0 : (t == 1) ? xr1 : (t == 2) ? xr2 : xr3;
            const int code = bi[t];
            atomicAdd(&hist[code], 1.0f);

            float qv[DIM];
            const float4* qrow = reinterpret_cast<const float4*>(cb + code * DIM);
            #pragma unroll
            for (int j = 0; j < 8; j++) {
                float4 v = __ldg(qrow + j);
                qv[4*j+0] = v.x; qv[4*j+1] = v.y; qv[4*j+2] = v.z; qv[4*j+3] = v.w;
            }

            float q2 = 0.f, dotq = 0.f;
            #pragma unroll
            for (int d = 0; d < DIM; d++) {
                q2   = __fmaf_rn(qv[d], qv[d], q2);
                dotq = __fmaf_rn(xrt[d], qv[d], dotq);
            }
            const float eps = 1e-6f;
            const float x2t = x2v[t];
            float inx = 1.0f / fmaxf(sqrtf(x2t), eps);
            float inq = 1.0f / fmaxf(sqrtf(q2),  eps);
            float u2  = x2t * inx * inx;
            float qh2 = q2  * inq * inq;
            float uq  = dotq * inx * inq;
            float w2  = u2 + qh2 + 2.0f * uq;
            float iw  = 1.0f / fmaxf(sqrtf(w2), eps);
            float ew_un = x2t * inx + dotq * inq;
            float ew  = ew_un * iw;
            float eu  = x2t * inx;
            float a   = -2.0f * ew * iw;
            float s1  = 1.0f + a * inx;
            float s2  = (a + 2.0f * eu) * inq;

            float4* rp = reinterpret_cast<float4*>(out_rot + ((long long)q * 4 + t) * DIM);
            #pragma unroll
            for (int j = 0; j < 8; j++) {
                float4 v;
                v.x = xrt[4*j+0] * s1 + qv[4*j+0] * s2;
                v.y = xrt[4*j+1] * s1 + qv[4*j+1] * s2;
                v.z = xrt[4*j+2] * s1 + qv[4*j+2] * s2;
                v.w = xrt[4*j+3] * s1 + qv[4*j+3] * s2;
                rp[j] = v;
            }
            out_idx[(long long)q * 4 + t] = (float)code;
        }
    }

    // --- Flush block-local histogram ---
    __syncthreads();
    for (int k = tid; k < KCODES; k += TPB)
        atomicAdd(&out_counts[k], hist[k]);
}

extern "C" void kernel_launch(void* const* d_in, const int* in_sizes, int n_in,
                              void* d_out, int out_size) {
    const float* x  = (const float*)d_in[0];
    const float* cb = (const float*)d_in[1];
    float* out = (float*)d_out;

    const int N = in_sizes[0] / DIM;            // 524288
    const int nQuads = N / 4;                   // 131072
    float* rot    = out;
    float* idx    = out + (size_t)N * DIM;
    float* counts = idx + N;

    cudaMemcpyToSymbolAsync(cb_c, cb, KCODES * DIM * sizeof(float), 0,
                            cudaMemcpyDeviceToDevice, 0);
    vq_zero_counts<<<1, KCODES>>>(counts);
    vq_main<<<NBLOCKS, TPB>>>(x, cb, rot, idx, counts, nQuads);
}

// round 7
// speedup vs baseline: 1.3372x; 1.0903x over previous
#include <cuda_runtime.h>

#define KCODES 256
#define DIM 32
#define TPB 128
#define NBLOCKS 456      // 3 CTAs/SM on 152 SMs -> single wave

__global__ void vq_zero_counts(float* counts) {
    counts[threadIdx.x] = 0.0f;
}

// 8-way chain-interleaved FMA block (>= 8 instrs between same-chain uses).
#define FMA8(d, aval, bval)                                   \
    da0 = __fmaf_rn(xr0[d], (aval), da0);                     \
    da1 = __fmaf_rn(xr1[d], (aval), da1);                     \
    da2 = __fmaf_rn(xr2[d], (aval), da2);                     \
    da3 = __fmaf_rn(xr3[d], (aval), da3);                     \
    db0 = __fmaf_rn(xr0[d], (bval), db0);                     \
    db1 = __fmaf_rn(xr1[d], (bval), db1);                     \
    db2 = __fmaf_rn(xr2[d], (bval), db2);                     \
    db3 = __fmaf_rn(xr3[d], (bval), db3);

__global__ __launch_bounds__(TPB, 3) void vq_main(
    const float* __restrict__ x,
    const float* __restrict__ cb,
    float* __restrict__ out_rot,
    float* __restrict__ out_idx,
    float* __restrict__ out_counts,
    int nQuads)
{
    __shared__ __align__(16) float cb_s[KCODES * DIM];   // full codebook, 32 KB
    __shared__ float c2_s[KCODES];
    __shared__ float hist[KCODES];

    const int tid = threadIdx.x;

    // --- Stage full codebook into shared; c2 exact (rounded squares, seq sum) ---
    for (int k = tid; k < KCODES; k += TPB) {
        const float4* src = reinterpret_cast<const float4*>(cb + k * DIM);
        float4* dst = reinterpret_cast<float4*>(cb_s + k * DIM);
        float row[DIM];
        #pragma unroll
        for (int j = 0; j < 8; j++) {
            float4 v = src[j];
            row[4*j+0] = v.x; row[4*j+1] = v.y; row[4*j+2] = v.z; row[4*j+3] = v.w;
            dst[j] = v;
        }
        float s = 0.0f;
        #pragma unroll
        for (int d = 0; d < DIM; d++)
            s = __fadd_rn(s, __fmul_rn(row[d], row[d]));
        c2_s[k] = s;
        hist[k] = 0.0f;
    }
    __syncthreads();

    const int qs = (int)(((long long)blockIdx.x * nQuads) / NBLOCKS);
    const int qe = (int)(((long long)(blockIdx.x + 1) * nQuads) / NBLOCKS);

    for (int q = qs + tid; q < qe; q += TPB) {
        const float* xb = x + (long long)q * (4 * DIM);

        // Four tokens in registers; x2 sequential ascending d (reference order).
        float xr0[DIM], xr1[DIM], xr2[DIM], xr3[DIM];
        float x2v[4];
        {
            #pragma unroll
            for (int j = 0; j < 8; j++) {
                float4 v0 = reinterpret_cast<const float4*>(xb        )[j];
                float4 v1 = reinterpret_cast<const float4*>(xb +   DIM)[j];
                float4 v2 = reinterpret_cast<const float4*>(xb + 2*DIM)[j];
                float4 v3 = reinterpret_cast<const float4*>(xb + 3*DIM)[j];
                xr0[4*j+0]=v0.x; xr0[4*j+1]=v0.y; xr0[4*j+2]=v0.z; xr0[4*j+3]=v0.w;
                xr1[4*j+0]=v1.x; xr1[4*j+1]=v1.y; xr1[4*j+2]=v1.z; xr1[4*j+3]=v1.w;
                xr2[4*j+0]=v2.x; xr2[4*j+1]=v2.y; xr2[4*j+2]=v2.z; xr2[4*j+3]=v2.w;
                xr3[4*j+0]=v3.x; xr3[4*j+1]=v3.y; xr3[4*j+2]=v3.z; xr3[4*j+3]=v3.w;
            }
            float s0=0.f, s1=0.f, s2=0.f, s3=0.f;
            #pragma unroll
            for (int d = 0; d < DIM; d++) {
                s0 = __fadd_rn(s0, __fmul_rn(xr0[d], xr0[d]));
                s1 = __fadd_rn(s1, __fmul_rn(xr1[d], xr1[d]));
                s2 = __fadd_rn(s2, __fmul_rn(xr2[d], xr2[d]));
                s3 = __fadd_rn(s3, __fmul_rn(xr3[d], xr3[d]));
            }
            x2v[0]=s0; x2v[1]=s1; x2v[2]=s2; x2v[3]=s3;
        }

        float best[4] = {3.4e38f, 3.4e38f, 3.4e38f, 3.4e38f};
        int   bi[4]   = {0, 0, 0, 0};

        // --- Argmin scan: 2 codes/iter × 4 tokens, all dims from shared ---
        #pragma unroll 1
        for (int k = 0; k < KCODES; k += 2) {
            float da0=0.f, da1=0.f, da2=0.f, da3=0.f;
            float db0=0.f, db1=0.f, db2=0.f, db3=0.f;

            #pragma unroll
            for (int jj = 0; jj < 8; jj++) {
                float4 ca = reinterpret_cast<const float4*>(cb_s +  k      * DIM)[jj];
                float4 cc = reinterpret_cast<const float4*>(cb_s + (k + 1) * DIM)[jj];
                const int d = 4 * jj;
                FMA8(d + 0, ca.x, cc.x)
                FMA8(d + 1, ca.y, cc.y)
                FMA8(d + 2, ca.z, cc.z)
                FMA8(d + 3, ca.w, cc.w)
            }

            // d2 = fl(fl(x2 - 2*dot) + c2); strict <, ascending k = first-index ties
            const float c2a = c2_s[k], c2b = c2_s[k + 1];
            float va0 = __fadd_rn(__fadd_rn(x2v[0], __fmul_rn(-2.0f, da0)), c2a);
            float va1 = __fadd_rn(__fadd_rn(x2v[1], __fmul_rn(-2.0f, da1)), c2a);
            float va2 = __fadd_rn(__fadd_rn(x2v[2], __fmul_rn(-2.0f, da2)), c2a);
            float va3 = __fadd_rn(__fadd_rn(x2v[3], __fmul_rn(-2.0f, da3)), c2a);
            float vb0 = __fadd_rn(__fadd_rn(x2v[0], __fmul_rn(-2.0f, db0)), c2b);
            float vb1 = __fadd_rn(__fadd_rn(x2v[1], __fmul_rn(-2.0f, db1)), c2b);
            float vb2 = __fadd_rn(__fadd_rn(x2v[2], __fmul_rn(-2.0f, db2)), c2b);
            float vb3 = __fadd_rn(__fadd_rn(x2v[3], __fmul_rn(-2.0f, db3)), c2b);
            bool u;
            u = va0 < best[0]; best[0] = u ? va0 : best[0]; bi[0] = u ? k : bi[0];
            u = va1 < best[1]; best[1] = u ? va1 : best[1]; bi[1] = u ? k : bi[1];
            u = va2 < best[2]; best[2] = u ? va2 : best[2]; bi[2] = u ? k : bi[2];
            u = va3 < best[3]; best[3] = u ? va3 : best[3]; bi[3] = u ? k : bi[3];
            u = vb0 < best[0]; best[0] = u ? vb0 : best[0]; bi[0] = u ? k+1 : bi[0];
            u = vb1 < best[1]; best[1] = u ? vb1 : best[1]; bi[1] = u ? k+1 : bi[1];
            u = vb2 < best[2]; best[2] = u ? vb2 : best[2]; bi[2] = u ? k+1 : bi[2];
            u = vb3 < best[3]; best[3] = u ? vb3 : best[3]; bi[3] = u ? k+1 : bi[3];
        }

        // --- Per-token epilogue: histogram + rotation-trick output ---
        #pragma unroll
        for (int t = 0; t < 4; t++) {
            const float* xrt = (t == 0) ? xr0 : (t == 1) ? xr1 : (t == 2) ? xr2 : xr3;
            const int code = bi[t];
            atomicAdd(&hist[code], 1.0f);

            float qv[DIM];
            const float4* qrow = reinterpret_cast<const float4*>(cb + code * DIM);
            #pragma unroll
            for (int j = 0; j < 8; j++) {
                float4 v = __ldg(qrow + j);
                qv[4*j+0] = v.x; qv[4*j+1] = v.y; qv[4*j+2] = v.z; qv[4*j+3] = v.w;
            }

            float q2 = 0.f, dotq = 0.f;
            #pragma unroll
            for (int d = 0; d < DIM; d++) {
                q2   = __fmaf_rn(qv[d], qv[d], q2);
                dotq = __fmaf_rn(xrt[d], qv[d], dotq);
            }
            const float eps = 1e-6f;
            const float x2t = x2v[t];
            float inx = 1.0f / fmaxf(sqrtf(x2t), eps);
            float inq = 1.0f / fmaxf(sqrtf(q2),  eps);
            float u2  = x2t * inx * inx;
            float qh2 = q2  * inq * inq;
            float uq  = dotq * inx * inq;
            float w2  = u2 + qh2 + 2.0f * uq;
            float iw  = 1.0f / fmaxf(sqrtf(w2), eps);
            float ew_un = x2t * inx + dotq * inq;
            float ew  = ew_un * iw;
            float eu  = x2t * inx;
            float a   = -2.0f * ew * iw;
            float s1  = 1.0f + a * inx;
            float s2  = (a + 2.0f * eu) * inq;

            float4* rp = reinterpret_cast<float4*>(out_rot + ((long long)q * 4 + t) * DIM);
            #pragma unroll
            for (int j = 0; j < 8; j++) {
                float4 v;
                v.x = xrt[4*j+0] * s1 + qv[4*j+0] * s2;
                v.y = xrt[4*j+1] * s1 + qv[4*j+1] * s2;
                v.z = xrt[4*j+2] * s1 + qv[4*j+2] * s2;
                v.w = xrt[4*j+3] * s1 + qv[4*j+3] * s2;
                rp[j] = v;
            }
            out_idx[(long long)q * 4 + t] = (float)code;
        }
    }

    // --- Flush block-local histogram ---
    __syncthreads();
    for (int k = tid; k < KCODES; k += TPB)
        atomicAdd(&out_counts[k], hist[k]);
}

extern "C" void kernel_launch(void* const* d_in, const int* in_sizes, int n_in,
                              void* d_out, int out_size) {
    const float* x  = (const float*)d_in[0];
    const float* cb = (const float*)d_in[1];
    float* out = (float*)d_out;

    const int N = in_sizes[0] / DIM;            // 524288
    const int nQuads = N / 4;                   // 131072
    float* rot    = out;
    float* idx    = out + (size_t)N * DIM;
    float* counts = idx + N;

    vq_zero_counts<<<1, KCODES>>>(counts);
    vq_main<<<NBLOCKS, TPB>>>(x, cb, rot, idx, counts, nQuads);
}

// round 8
// speedup vs baseline: 1.3508x; 1.0102x over previous
#include <cuda_runtime.h>

#define KCODES 256
#define DIM 32
#define TPB 128
#define NBLOCKS 456      // 3 CTAs/SM on 152 SMs -> single wave

__global__ void vq_zero_counts(float* counts) {
    counts[threadIdx.x] = 0.0f;
}

// 4-token FMA update for one code-scalar against one accumulator set.
#define FMA4(acc0, acc1, acc2, acc3, d, cval)        \
    acc0 = __fmaf_rn(xr0[d], (cval), acc0);          \
    acc1 = __fmaf_rn(xr1[d], (cval), acc1);          \
    acc2 = __fmaf_rn(xr2[d], (cval), acc2);          \
    acc3 = __fmaf_rn(xr3[d], (cval), acc3);

// Compare one code's 4 d2 values against best, ascending-k order preserved
// by call order. d2 = fl(fl(x2 - 2*dot) + c2); strict < = first-index ties.
#define CMP4(acc0, acc1, acc2, acc3, c2v, kidx)                                \
    {                                                                          \
        float v0 = __fadd_rn(__fadd_rn(x2v[0], __fmul_rn(-2.0f, acc0)), c2v);  \
        float v1 = __fadd_rn(__fadd_rn(x2v[1], __fmul_rn(-2.0f, acc1)), c2v);  \
        float v2 = __fadd_rn(__fadd_rn(x2v[2], __fmul_rn(-2.0f, acc2)), c2v);  \
        float v3 = __fadd_rn(__fadd_rn(x2v[3], __fmul_rn(-2.0f, acc3)), c2v);  \
        bool u;                                                                \
        u = v0 < best[0]; best[0] = u ? v0 : best[0]; bi[0] = u ? (kidx) : bi[0]; \
        u = v1 < best[1]; best[1] = u ? v1 : best[1]; bi[1] = u ? (kidx) : bi[1]; \
        u = v2 < best[2]; best[2] = u ? v2 : best[2]; bi[2] = u ? (kidx) : bi[2]; \
        u = v3 < best[3]; best[3] = u ? v3 : best[3]; bi[3] = u ? (kidx) : bi[3]; \
    }

__global__ __launch_bounds__(TPB, 3) void vq_main(
    const float* __restrict__ x,
    const float* __restrict__ cb,
    float* __restrict__ out_rot,
    float* __restrict__ out_idx,
    float* __restrict__ out_counts,
    int nQuads)
{
    __shared__ __align__(16) float cb_s[KCODES * DIM];   // full codebook, 32 KB
    __shared__ float c2_s[KCODES];
    __shared__ float hist[KCODES];

    const int tid = threadIdx.x;

    // --- Stage full codebook into shared; c2 exact (rounded squares, seq sum) ---
    for (int k = tid; k < KCODES; k += TPB) {
        const float4* src = reinterpret_cast<const float4*>(cb + k * DIM);
        float4* dst = reinterpret_cast<float4*>(cb_s + k * DIM);
        float row[DIM];
        #pragma unroll
        for (int j = 0; j < 8; j++) {
            float4 v = src[j];
            row[4*j+0] = v.x; row[4*j+1] = v.y; row[4*j+2] = v.z; row[4*j+3] = v.w;
            dst[j] = v;
        }
        float s = 0.0f;
        #pragma unroll
        for (int d = 0; d < DIM; d++)
            s = __fadd_rn(s, __fmul_rn(row[d], row[d]));
        c2_s[k] = s;
        hist[k] = 0.0f;
    }
    __syncthreads();

    const int qs = (int)(((long long)blockIdx.x * nQuads) / NBLOCKS);
    const int qe = (int)(((long long)(blockIdx.x + 1) * nQuads) / NBLOCKS);

    for (int q = qs + tid; q < qe; q += TPB) {
        const float* xb = x + (long long)q * (4 * DIM);

        // Four tokens in registers; x2 sequential ascending d (reference order).
        float xr0[DIM], xr1[DIM], xr2[DIM], xr3[DIM];
        float x2v[4];
        {
            #pragma unroll
            for (int j = 0; j < 8; j++) {
                float4 v0 = reinterpret_cast<const float4*>(xb        )[j];
                float4 v1 = reinterpret_cast<const float4*>(xb +   DIM)[j];
                float4 v2 = reinterpret_cast<const float4*>(xb + 2*DIM)[j];
                float4 v3 = reinterpret_cast<const float4*>(xb + 3*DIM)[j];
                xr0[4*j+0]=v0.x; xr0[4*j+1]=v0.y; xr0[4*j+2]=v0.z; xr0[4*j+3]=v0.w;
                xr1[4*j+0]=v1.x; xr1[4*j+1]=v1.y; xr1[4*j+2]=v1.z; xr1[4*j+3]=v1.w;
                xr2[4*j+0]=v2.x; xr2[4*j+1]=v2.y; xr2[4*j+2]=v2.z; xr2[4*j+3]=v2.w;
                xr3[4*j+0]=v3.x; xr3[4*j+1]=v3.y; xr3[4*j+2]=v3.z; xr3[4*j+3]=v3.w;
            }
            float s0=0.f, s1=0.f, s2=0.f, s3=0.f;
            #pragma unroll
            for (int d = 0; d < DIM; d++) {
                s0 = __fadd_rn(s0, __fmul_rn(xr0[d], xr0[d]));
                s1 = __fadd_rn(s1, __fmul_rn(xr1[d], xr1[d]));
                s2 = __fadd_rn(s2, __fmul_rn(xr2[d], xr2[d]));
                s3 = __fadd_rn(s3, __fmul_rn(xr3[d], xr3[d]));
            }
            x2v[0]=s0; x2v[1]=s1; x2v[2]=s2; x2v[3]=s3;
        }

        float best[4] = {3.4e38f, 3.4e38f, 3.4e38f, 3.4e38f};
        int   bi[4]   = {0, 0, 0, 0};

        // --- Argmin scan: 4 codes/iter × 4 tokens, all dims from shared ---
        #pragma unroll 1
        for (int k = 0; k < KCODES; k += 4) {
            float da0=0.f, da1=0.f, da2=0.f, da3=0.f;   // code k
            float db0=0.f, db1=0.f, db2=0.f, db3=0.f;   // code k+1
            float dc0=0.f, dc1=0.f, dc2=0.f, dc3=0.f;   // code k+2
            float dd0=0.f, dd1=0.f, dd2=0.f, dd3=0.f;   // code k+3

            #pragma unroll
            for (int jj = 0; jj < 8; jj++) {
                float4 ca = reinterpret_cast<const float4*>(cb_s +  k      * DIM)[jj];
                float4 cc = reinterpret_cast<const float4*>(cb_s + (k + 1) * DIM)[jj];
                float4 ce = reinterpret_cast<const float4*>(cb_s + (k + 2) * DIM)[jj];
                float4 cg = reinterpret_cast<const float4*>(cb_s + (k + 3) * DIM)[jj];
                const int d = 4 * jj;
                FMA4(da0, da1, da2, da3, d + 0, ca.x)
                FMA4(db0, db1, db2, db3, d + 0, cc.x)
                FMA4(dc0, dc1, dc2, dc3, d + 0, ce.x)
                FMA4(dd0, dd1, dd2, dd3, d + 0, cg.x)
                FMA4(da0, da1, da2, da3, d + 1, ca.y)
                FMA4(db0, db1, db2, db3, d + 1, cc.y)
                FMA4(dc0, dc1, dc2, dc3, d + 1, ce.y)
                FMA4(dd0, dd1, dd2, dd3, d + 1, cg.y)
                FMA4(da0, da1, da2, da3, d + 2, ca.z)
                FMA4(db0, db1, db2, db3, d + 2, cc.z)
                FMA4(dc0, dc1, dc2, dc3, d + 2, ce.z)
                FMA4(dd0, dd1, dd2, dd3, d + 2, cg.z)
                FMA4(da0, da1, da2, da3, d + 3, ca.w)
                FMA4(db0, db1, db2, db3, d + 3, cc.w)
                FMA4(dc0, dc1, dc2, dc3, d + 3, ce.w)
                FMA4(dd0, dd1, dd2, dd3, d + 3, cg.w)
            }

            CMP4(da0, da1, da2, da3, c2_s[k],     k)
            CMP4(db0, db1, db2, db3, c2_s[k + 1], k + 1)
            CMP4(dc0, dc1, dc2, dc3, c2_s[k + 2], k + 2)
            CMP4(dd0, dd1, dd2, dd3, c2_s[k + 3], k + 3)
        }

        // --- Per-token epilogue: histogram + rotation-trick output ---
        #pragma unroll
        for (int t = 0; t < 4; t++) {
            const float* xrt = (t == 0) ? xr0 : (t == 1) ? xr1 : (t == 2) ? xr2 : xr3;
            const int code = bi[t];
            atomicAdd(&hist[code], 1.0f);

            float qv[DIM];
            const float4* qrow = reinterpret_cast<const float4*>(cb + code * DIM);
            #pragma unroll
            for (int j = 0; j < 8; j++) {
                float4 v = __ldg(qrow + j);
                qv[4*j+0] = v.x; qv[4*j+1] = v.y; qv[4*j+2] = v.z; qv[4*j+3] = v.w;
            }

            float q2 = 0.f, dotq = 0.f;
            #pragma unroll
            for (int d = 0; d < DIM; d++) {
                q2   = __fmaf_rn(qv[d], qv[d], q2);
                dotq = __fmaf_rn(xrt[d], qv[d], dotq);
            }
            const float eps = 1e-6f;
            const float x2t = x2v[t];
            float inx = 1.0f / fmaxf(sqrtf(x2t), eps);
            float inq = 1.0f / fmaxf(sqrtf(q2),  eps);
            float u2  = x2t * inx * inx;
            float qh2 = q2  * inq * inq;
            float uq  = dotq * inx * inq;
            float w2  = u2 + qh2 + 2.0f * uq;
            float iw  = 1.0f / fmaxf(sqrtf(w2), eps);
            float ew_un = x2t * inx + dotq * inq;
            float ew  = ew_un * iw;
            float eu  = x2t * inx;
            float a   = -2.0f * ew * iw;
            float s1  = 1.0f + a * inx;
            float s2  = (a + 2.0f * eu) * inq;

            float4* rp = reinterpret_cast<float4*>(out_rot + ((long long)q * 4 + t) * DIM);
            #pragma unroll
            for (int j = 0; j < 8; j++) {
                float4 v;
                v.x = xrt[4*j+0] * s1 + qv[4*j+0] * s2;
                v.y = xrt[4*j+1] * s1 + qv[4*j+1] * s2;
                v.z = xrt[4*j+2] * s1 + qv[4*j+2] * s2;
                v.w = xrt[4*j+3] * s1 + qv[4*j+3] * s2;
                rp[j] = v;
            }
            out_idx[(long long)q * 4 + t] = (float)code;
        }
    }

    // --- Flush block-local histogram ---
    __syncthreads();
    for (int k = tid; k < KCODES; k += TPB)
        atomicAdd(&out_counts[k], hist[k]);
}

extern "C" void kernel_launch(void* const* d_in, const int* in_sizes, int n_in,
                              void* d_out, int out_size) {
    const float* x  = (const float*)d_in[0];
    const float* cb = (const float*)d_in[1];
    float* out = (float*)d_out;

    const int N = in_sizes[0] / DIM;            // 524288
    const int nQuads = N / 4;                   // 131072
    float* rot    = out;
    float* idx    = out + (size_t)N * DIM;
    float* counts = idx + N;

    vq_zero_counts<<<1, KCODES>>>(counts);
    vq_main<<<NBLOCKS, TPB>>>(x, cb, rot, idx, counts, nQuads);
}